// round 2
// baseline (speedup 1.0000x reference)
#include <cuda_runtime.h>

// Problem constants
#define B_   8
#define C_   512
#define H_   14
#define W_   14
#define P_   196      // H*W positions
#define HS_  1024
#define KC_  144      // 12x12 centers

// Scratch: projections of ALL 196 positions with w1 and w2.
// side_proj[o,b,k,:] == g_q2[b, pos(k)+offset(o), :]  (key restructuring)
__device__ float g_q1[B_ * P_ * HS_];
__device__ float g_q2[B_ * P_ * HS_];

// ---- packed f32x2 helpers (2 FMAs per issue slot on sm_103a) ----
__device__ __forceinline__ unsigned long long pack2(float lo, float hi) {
    unsigned long long r;
    asm("mov.b64 %0, {%1, %2};" : "=l"(r) : "f"(lo), "f"(hi));
    return r;
}
__device__ __forceinline__ void unpack2(unsigned long long v, float& lo, float& hi) {
    asm("mov.b64 {%0, %1}, %2;" : "=f"(lo), "=f"(hi) : "l"(v));
}
__device__ __forceinline__ void fma2(unsigned long long& d, unsigned long long a, unsigned long long b) {
    asm("fma.rn.f32x2 %0, %1, %2, %0;" : "+l"(d) : "l"(a), "l"(b));
}

// =====================================================================
// Phase 1: q[b,p,h] = sum_c x[b,c,p] * w[h,c] + bias[h] for all 196 p.
// Tile: 32 positions x 128 h per CTA, K-chunk 32. 256 threads,
// each thread 2 pos x 8 h (strided j mapping -> conflict-free LDS).
// =====================================================================
__global__ __launch_bounds__(256) void proj_kernel(
    const float* __restrict__ x,
    const float* __restrict__ w1, const float* __restrict__ b1,
    const float* __restrict__ w2, const float* __restrict__ b2)
{
    const int nt  = blockIdx.x;          // 8 h-tiles of 128
    const int mt  = blockIdx.y;          // 7 p-tiles of 32 (224 padded)
    const int b   = blockIdx.z >> 1;
    const int sel = blockIdx.z & 1;
    const float* w    = sel ? w2 : w1;
    const float* bias = sel ? b2 : b1;
    float* q = sel ? g_q2 : g_q1;

    __shared__ float As[32][32];     // [c'][p']
    __shared__ float Ws[32][129];    // [c'][h'] padded (stride 129 -> conflict-free)

    const int tid = threadIdx.x;
    const int tx = tid & 15, ty = tid >> 4;
    const int p0 = mt * 32, h0 = nt * 128;
    const float* xb = x + (size_t)b * C_ * P_;

    unsigned long long acc[2][4];
#pragma unroll
    for (int m = 0; m < 2; m++)
#pragma unroll
        for (int t = 0; t < 4; t++) acc[m][t] = 0ull;

    for (int c0 = 0; c0 < C_; c0 += 32) {
        __syncthreads();
#pragma unroll
        for (int r = 0; r < 4; r++) {            // 32x32 x-tile
            int i  = tid + 256 * r;
            int cc = i >> 5, pp = i & 31;
            int p  = p0 + pp;
            As[cc][pp] = (p < P_) ? xb[(size_t)(c0 + cc) * P_ + p] : 0.f;
        }
#pragma unroll
        for (int r = 0; r < 16; r++) {           // 128h x 32c w-tile (transposed store)
            int i  = tid + 256 * r;
            int cc = i & 31, hh = i >> 5;
            Ws[cc][hh] = w[(size_t)(h0 + hh) * C_ + c0 + cc];
        }
        __syncthreads();
#pragma unroll
        for (int kk = 0; kk < 32; kk++) {
            float a0 = As[kk][ty * 2 + 0], a1 = As[kk][ty * 2 + 1];
            unsigned long long A0 = pack2(a0, a0), A1 = pack2(a1, a1);
#pragma unroll
            for (int tp = 0; tp < 4; tp++) {
                unsigned long long Bp = pack2(Ws[kk][tx + 32 * tp], Ws[kk][tx + 32 * tp + 16]);
                fma2(acc[0][tp], A0, Bp);
                fma2(acc[1][tp], A1, Bp);
            }
        }
    }

#pragma unroll
    for (int m = 0; m < 2; m++) {
        int p = p0 + ty * 2 + m;
        if (p < P_) {
            float* qrow = q + ((size_t)b * P_ + p) * HS_;
#pragma unroll
            for (int tp = 0; tp < 4; tp++) {
                float lo, hi; unpack2(acc[m][tp], lo, hi);
                int hL = h0 + tx + 32 * tp, hH = hL + 16;
                qrow[hL] = lo + bias[hL];
                qrow[hH] = hi + bias[hH];
            }
        }
    }
}

// =====================================================================
// Phase 2: cofe[b,o,i,j] = sum_k q1[b,pc(k),i] * q2[b,ps(k,o),j],
// then row-normalize over j (L2-norm, eps=1e-12).
// CTA = 64 i-rows x full j=1024 (8 chunks of 128). Per-row sumsq kept
// in smem across chunks; raw tile written to gmem (stays L2-hot),
// re-read and scaled in place after the norm is known.
// =====================================================================
__global__ __launch_bounds__(256) void cofe_kernel(float* __restrict__ out)
{
    const int it = blockIdx.x;           // 16 i-tiles of 64
    const int bo = blockIdx.y;           // 72 (b,o) pairs
    const int b  = bo / 9, o = bo % 9;
    const int dy = o / 3 - 1, dx = o % 3 - 1;

    __shared__ float As[16][64];         // q1 tile [k'][i']
    __shared__ float Bs[16][128];        // q2 tile [k'][j']
    __shared__ float ssq[64];

    const int tid = threadIdx.x;
    const int tx = tid & 15, ty = tid >> 4;
    const int i0 = it * 64;
    const float* q1b = g_q1 + (size_t)b * P_ * HS_;
    const float* q2b = g_q2 + (size_t)b * P_ * HS_;
    float* outbo = out + (size_t)bo * HS_ * HS_;

    if (tid < 64) ssq[tid] = 0.f;

    for (int jc = 0; jc < 8; jc++) {
        const int j0 = jc * 128;
        unsigned long long acc[4][4];
#pragma unroll
        for (int m = 0; m < 4; m++)
#pragma unroll
            for (int t = 0; t < 4; t++) acc[m][t] = 0ull;

        for (int k0 = 0; k0 < KC_; k0 += 16) {
            __syncthreads();
#pragma unroll
            for (int r = 0; r < 4; r++) {        // 16k x 64i q1-tile (gather centers)
                int i  = tid + 256 * r;
                int kk = i >> 6, ii = i & 63;
                int k  = k0 + kk;
                int ky = k / 12, kx = k - ky * 12;
                int pos = (ky + 1) * 14 + (kx + 1);
                As[kk][ii] = q1b[(size_t)pos * HS_ + i0 + ii];
            }
#pragma unroll
            for (int r = 0; r < 8; r++) {        // 16k x 128j q2-tile (gather shifted)
                int i  = tid + 256 * r;
                int kk = i >> 7, jj = i & 127;
                int k  = k0 + kk;
                int ky = k / 12, kx = k - ky * 12;
                int pos = (ky + 1 + dy) * 14 + (kx + 1 + dx);
                Bs[kk][jj] = q2b[(size_t)pos * HS_ + j0 + jj];
            }
            __syncthreads();
#pragma unroll
            for (int kk = 0; kk < 16; kk++) {
                unsigned long long A[4], Bp[4];
#pragma unroll
                for (int m = 0; m < 4; m++) {
                    float a = As[kk][ty * 4 + m];
                    A[m] = pack2(a, a);
                }
#pragma unroll
                for (int tp = 0; tp < 4; tp++)
                    Bp[tp] = pack2(Bs[kk][tx + 32 * tp], Bs[kk][tx + 32 * tp + 16]);
#pragma unroll
                for (int m = 0; m < 4; m++)
#pragma unroll
                    for (int tp = 0; tp < 4; tp++)
                        fma2(acc[m][tp], A[m], Bp[tp]);
            }
        }

        // raw write + per-row sum of squares
#pragma unroll
        for (int m = 0; m < 4; m++) {
            float s = 0.f;
            float* orow = outbo + (size_t)(i0 + ty * 4 + m) * HS_ + j0;
#pragma unroll
            for (int tp = 0; tp < 4; tp++) {
                float lo, hi; unpack2(acc[m][tp], lo, hi);
                s += lo * lo + hi * hi;
                orow[tx + 32 * tp]      = lo;
                orow[tx + 32 * tp + 16] = hi;
            }
#pragma unroll
            for (int off = 1; off < 16; off <<= 1)
                s += __shfl_xor_sync(0xffffffffu, s, off, 16);
            if (tx == 0) ssq[ty * 4 + m] += s;   // unique (thread,row) owner -> race-free
        }
    }

    __syncthreads();     // raw writes + ssq visible block-wide
    if (tid < 64) {
        float n = sqrtf(ssq[tid]);
        ssq[tid] = 1.f / fmaxf(n, 1e-12f);
    }
    __syncthreads();

    // scale in place; stripe (256KB) is L2-resident
    float4* g4 = (float4*)(outbo + (size_t)i0 * HS_);
    for (int idx = tid; idx < 64 * HS_ / 4; idx += 256) {
        float4 v = g4[idx];
        float inv = ssq[idx >> 8];               // row = (idx*4)/1024
        v.x *= inv; v.y *= inv; v.z *= inv; v.w *= inv;
        g4[idx] = v;
    }
}

extern "C" void kernel_launch(void* const* d_in, const int* in_sizes, int n_in,
                              void* d_out, int out_size)
{
    const float* x  = (const float*)d_in[0];
    const float* w1 = (const float*)d_in[1];
    const float* b1 = (const float*)d_in[2];
    const float* w2 = (const float*)d_in[3];
    const float* b2 = (const float*)d_in[4];
    float* out = (float*)d_out;

    proj_kernel<<<dim3(8, 7, 16), 256>>>(x, w1, b1, w2, b2);
    cofe_kernel<<<dim3(16, 72), 256>>>(out);
}